// round 1
// baseline (speedup 1.0000x reference)
#include <cuda_runtime.h>
#include <cuda_bf16.h>
#include <cstdint>

// Problem constants
#define OBS 64
#define ACTD 8
#define DDIM 256
#define SDIM 32
#define HDIM 256
#define BSZ 1024
#define TSTEPS 128
#define GDIM 768           // 3*D
#define TMPN 1280          // D(prior) + D(post-h) + 3D(gru)
#define OUTW 416           // D + 5*S
#define NROWS (BSZ*TSTEPS) // 131072

// ---------------- device scratch (allowed: static __device__ arrays) ----------------
__device__ float g_h[BSZ * DDIM];            // 1 MB
__device__ float g_tmp[BSZ * TMPN];          // 5.2 MB
__device__ float g_Wcat[TMPN * DDIM];        // 1.3 MB
__device__ float g_E1[(size_t)NROWS * HDIM]; // 134 MB (reused as Q1E)
__device__ float g_E2[(size_t)NROWS * HDIM]; // 134 MB

// ---------------- generic NT GEMM: C = act(A @ W^T + bias) ----------------
// A: M x K (row stride lda), W: N x K (row stride ldw), C: M x N (row stride ldc)
// BM=BN=64, BK=16, 256 threads, 4x4 per thread. Assumes M%64==0, N%64==0, K%16==0,
// all pointers 16B aligned, lda/ldw/ldc multiples of 4.
#define BM 64
#define BN 64
#define BK 16

__global__ __launch_bounds__(256) void gemm_nt_kernel(
    const float* __restrict__ A, int lda,
    const float* __restrict__ W, int ldw,
    const float* __restrict__ bias,
    float* __restrict__ C, int ldc,
    int K, int actmode)
{
    __shared__ float As[BK][BM];
    __shared__ float Ws[BK][BN];

    const int tid = threadIdx.x;
    const int m0 = blockIdx.y * BM;
    const int n0 = blockIdx.x * BN;
    const int tx = tid & 15;          // 16 cols of threads
    const int ty = tid >> 4;          // 16 rows of threads
    const int lr = tid >> 2;          // 0..63  (tile row for loading)
    const int lk = (tid & 3) * 4;     // 0,4,8,12

    const float* Aptr = A + (size_t)(m0 + lr) * lda + lk;
    const float* Wptr = W + (size_t)(n0 + lr) * ldw + lk;

    float acc[4][4];
#pragma unroll
    for (int i = 0; i < 4; i++)
#pragma unroll
        for (int j = 0; j < 4; j++) acc[i][j] = 0.f;

    for (int k0 = 0; k0 < K; k0 += BK) {
        float4 av = *(const float4*)(Aptr + k0);
        float4 wv = *(const float4*)(Wptr + k0);
        __syncthreads();
        As[lk + 0][lr] = av.x; As[lk + 1][lr] = av.y;
        As[lk + 2][lr] = av.z; As[lk + 3][lr] = av.w;
        Ws[lk + 0][lr] = wv.x; Ws[lk + 1][lr] = wv.y;
        Ws[lk + 2][lr] = wv.z; Ws[lk + 3][lr] = wv.w;
        __syncthreads();
#pragma unroll
        for (int k = 0; k < BK; k++) {
            float4 a4 = *(const float4*)(&As[k][ty * 4]);
            float4 b4 = *(const float4*)(&Ws[k][tx * 4]);
            float ar[4] = {a4.x, a4.y, a4.z, a4.w};
            float br[4] = {b4.x, b4.y, b4.z, b4.w};
#pragma unroll
            for (int i = 0; i < 4; i++)
#pragma unroll
                for (int j = 0; j < 4; j++) acc[i][j] += ar[i] * br[j];
        }
    }

    float4 bb = make_float4(0.f, 0.f, 0.f, 0.f);
    if (bias) bb = *(const float4*)(bias + n0 + tx * 4);

#pragma unroll
    for (int i = 0; i < 4; i++) {
        int m = m0 + ty * 4 + i;
        float v0 = acc[i][0] + bb.x;
        float v1 = acc[i][1] + bb.y;
        float v2 = acc[i][2] + bb.z;
        float v3 = acc[i][3] + bb.w;
        if (actmode == 1) { // ELU
            v0 = v0 > 0.f ? v0 : expm1f(v0);
            v1 = v1 > 0.f ? v1 : expm1f(v1);
            v2 = v2 > 0.f ? v2 : expm1f(v2);
            v3 = v3 > 0.f ? v3 : expm1f(v3);
        }
        *(float4*)(C + (size_t)m * ldc + n0 + tx * 4) = make_float4(v0, v1, v2, v3);
    }
}

// ---------------- pack W_cat = [W_p1 ; W_q1[:, :D] ; W_hh] (1280 x 256) ----------------
__global__ void pack_wcat_kernel(const float* __restrict__ Wp1,
                                 const float* __restrict__ Wq1,
                                 const float* __restrict__ Whh)
{
    int idx = blockIdx.x * blockDim.x + threadIdx.x;
    int total = TMPN * DDIM;
    for (; idx < total; idx += gridDim.x * blockDim.x) {
        int j = idx / DDIM;
        int k = idx - j * DDIM;
        float v;
        if (j < 256)       v = Wp1[j * 256 + k];
        else if (j < 512)  v = Wq1[(j - 256) * 512 + k];   // h-part of W_q1 (ld 512)
        else               v = Whh[(j - 512) * 256 + k];
        g_Wcat[idx] = v;
    }
}

// ---------------- fused per-step kernel ----------------
// One block handles R=8 batch rows. 256 threads.
#define RPB 8

__device__ __forceinline__ float sigmf(float x) { return 1.f / (1.f + expf(-x)); }

__global__ __launch_bounds__(256) void step_kernel(
    int t,
    const float* __restrict__ q1e,     // [B*T, 256] : emb@Wq1e^T + b_q1
    const float* __restrict__ noise,   // [T, B, S]
    const float* __restrict__ act,     // [B, T, ACT]
    const float* __restrict__ Wp2, const float* __restrict__ bp2,  // (64,256),(64)
    const float* __restrict__ Wq2, const float* __restrict__ bq2,  // (64,256),(64)
    const float* __restrict__ bp1,                                  // (256)
    const float* __restrict__ Wih, const float* __restrict__ bih,  // (768,40),(768)
    const float* __restrict__ bhh,                                  // (768)
    float* __restrict__ out)           // [B, T, 416]
{
    __shared__ float PQ[2][RPB][256];  // [0]=elu(prior pre), [1]=elu(post pre)
    __shared__ float ST[RPB][128];     // pstats(64) | qstats(64)
    __shared__ float ZA[RPB][40];      // z(32) | act(8)

    const int tid = threadIdx.x;
    const int b0 = blockIdx.x * RPB;

    // ---- stage 1: load tmp, add biases, ELU ----
    for (int i = tid; i < RPB * 256; i += 256) {
        int r = i >> 8, d = i & 255;
        int b = b0 + r;
        const float* trow = g_tmp + (size_t)b * TMPN;
        float p = trow[d] + bp1[d];
        PQ[0][r][d] = p > 0.f ? p : expm1f(p);
        float q = trow[256 + d] + q1e[((size_t)b * TSTEPS + t) * 256 + d];
        PQ[1][r][d] = q > 0.f ? q : expm1f(q);
    }
    __syncthreads();

    // ---- stage 2: prior/posterior stats (dot-256 each) ----
    {
        int j = tid & 127;           // 0..63 -> pstats ; 64..127 -> qstats
        int rbase = tid >> 7;        // 0 or 1
        bool isq = (j >= 64);
        int jj = isq ? j - 64 : j;
        const float* wrow = (isq ? Wq2 : Wp2) + jj * 256;
        float bb = (isq ? bq2 : bp2)[jj];
        const float* base = &PQ[isq ? 1 : 0][0][0];

        float accm[4] = {0.f, 0.f, 0.f, 0.f};
        for (int k = 0; k < 256; k += 4) {
            float4 w = *(const float4*)(wrow + k);
#pragma unroll
            for (int m = 0; m < 4; m++) {
                int r = rbase + 2 * m;
                float4 s = *(const float4*)(base + r * 256 + k);
                accm[m] += s.x * w.x + s.y * w.y + s.z * w.z + s.w * w.w;
            }
        }
#pragma unroll
        for (int m = 0; m < 4; m++) ST[rbase + 2 * m][j] = accm[m] + bb;
    }
    __syncthreads();

    // ---- stage 3: z = qm + qs*eps ; stage act into smem ----
    {
        int r = tid >> 5, s = tid & 31;
        int b = b0 + r;
        float qm = ST[r][64 + s];
        float ql = fminf(fmaxf(ST[r][96 + s], -7.f), 5.f);
        float qs = expf(ql);
        float eps = noise[((size_t)t * BSZ + b) * SDIM + s];
        ZA[r][s] = qm + qs * eps;
    }
    if (tid < RPB * ACTD) {
        int r = tid >> 3, j = tid & 7;
        int b = b0 + r;
        ZA[r][32 + j] = act[((size_t)b * TSTEPS + t) * ACTD + j];
    }
    __syncthreads();

    // ---- stage 4: GRU gates + h update + write h_old to out ----
#pragma unroll 1
    for (int r = 0; r < RPB; r++) {
        int d = tid;
        int b = b0 + r;
        float gi[3];
#pragma unroll
        for (int g = 0; g < 3; g++) {
            const float* w = Wih + (size_t)(g * 256 + d) * 40;
            float a = 0.f;
#pragma unroll
            for (int k4 = 0; k4 < 10; k4++) {
                float4 wv = *(const float4*)(w + 4 * k4);
                float4 sv = *(const float4*)(&ZA[r][4 * k4]);
                a += sv.x * wv.x + sv.y * wv.y + sv.z * wv.z + sv.w * wv.w;
            }
            gi[g] = a + bih[g * 256 + d];
        }
        const float* trow = g_tmp + (size_t)b * TMPN + 512;
        float ghr = trow[d]        + bhh[d];
        float ghu = trow[256 + d]  + bhh[256 + d];
        float ghn = trow[512 + d]  + bhh[512 + d];
        float rg = sigmf(gi[0] + ghr);
        float u  = sigmf(gi[1] + ghu);
        float nn = tanhf(gi[2] + rg * ghn);
        float hold = g_h[(size_t)b * DDIM + d];
        float hnew = (1.f - u) * nn + u * hold;
        out[((size_t)b * TSTEPS + t) * OUTW + d] = hold;
        g_h[(size_t)b * DDIM + d] = hnew;
    }

    // ---- stage 5: write z, pm, ps, qm, qs ----
    for (int i = tid; i < RPB * 160; i += 256) {
        int r = i / 160, c = i - r * 160;
        int b = b0 + r;
        float v;
        if (c < 32) {
            v = ZA[r][c];
        } else {
            v = ST[r][c - 32];
            if ((c >= 64 && c < 96) || c >= 128) {
                v = expf(fminf(fmaxf(v, -7.f), 5.f));
            }
        }
        out[((size_t)b * TSTEPS + t) * OUTW + 256 + c] = v;
    }
}

// ---------------- host launch ----------------
extern "C" void kernel_launch(void* const* d_in, const int* in_sizes, int n_in,
                              void* d_out, int out_size)
{
    (void)in_sizes; (void)n_in; (void)out_size;
    const float* obs  = (const float*)d_in[0];   // [B,T,OBS]
    const float* actp = (const float*)d_in[1];   // [B,T,ACT]
    const float* noi  = (const float*)d_in[2];   // [T,B,S]
    const float* We1  = (const float*)d_in[3];   // (256,64)
    const float* be1  = (const float*)d_in[4];
    const float* We2  = (const float*)d_in[5];   // (256,256)
    const float* be2  = (const float*)d_in[6];
    const float* Wih  = (const float*)d_in[7];   // (768,40)
    const float* Whh  = (const float*)d_in[8];   // (768,256)
    const float* bih  = (const float*)d_in[9];
    const float* bhh  = (const float*)d_in[10];
    const float* Wp1  = (const float*)d_in[11];  // (256,256)
    const float* bp1  = (const float*)d_in[12];
    const float* Wp2  = (const float*)d_in[13];  // (64,256)
    const float* bp2  = (const float*)d_in[14];
    const float* Wq1  = (const float*)d_in[15];  // (256,512)
    const float* bq1  = (const float*)d_in[16];
    const float* Wq2  = (const float*)d_in[17];  // (64,256)
    const float* bq2  = (const float*)d_in[18];
    float* out = (float*)d_out;

    float *p_h, *p_tmp, *p_Wcat, *p_E1, *p_E2;
    cudaGetSymbolAddress((void**)&p_h,    g_h);
    cudaGetSymbolAddress((void**)&p_tmp,  g_tmp);
    cudaGetSymbolAddress((void**)&p_Wcat, g_Wcat);
    cudaGetSymbolAddress((void**)&p_E1,   g_E1);
    cudaGetSymbolAddress((void**)&p_E2,   g_E2);

    // h0 = 0
    cudaMemsetAsync(p_h, 0, sizeof(float) * BSZ * DDIM, 0);

    // pack W_cat
    pack_wcat_kernel<<<320, 1024>>>(Wp1, Wq1, Whh);

    // Precompute: E1 = elu(obs@We1^T+be1) ; E2 = elu(E1@We2^T+be2) ;
    //             Q1E(=E1 buffer) = E2@Wq1[:,D:]^T + bq1
    {
        dim3 g1(HDIM / BN, NROWS / BM);
        gemm_nt_kernel<<<g1, 256>>>(obs, OBS, We1, OBS, be1, p_E1, HDIM, OBS, 1);
        gemm_nt_kernel<<<g1, 256>>>(p_E1, HDIM, We2, HDIM, be2, p_E2, HDIM, HDIM, 1);
        gemm_nt_kernel<<<g1, 256>>>(p_E2, HDIM, Wq1 + 256, 512, bq1, p_E1, HDIM, HDIM, 0);
    }

    // Sequential scan
    dim3 gk1(TMPN / BN, BSZ / BM);   // 20 x 16
    for (int t = 0; t < TSTEPS; t++) {
        gemm_nt_kernel<<<gk1, 256>>>(p_h, DDIM, p_Wcat, DDIM, nullptr,
                                     p_tmp, TMPN, DDIM, 0);
        step_kernel<<<BSZ / RPB, 256>>>(t, p_E1, noi, actp,
                                        Wp2, bp2, Wq2, bq2, bp1,
                                        Wih, bih, bhh, out);
    }
}